// round 10
// baseline (speedup 1.0000x reference)
#include <cuda_runtime.h>
#include <cuda_bf16.h>
#include <math.h>

// ---------------- problem constants ----------------
#define B_IMG   64
#define HW      416
#define P1      206          // pooled1 spatial (412/2)
#define P2      101          // pooled2 spatial (202/2)
#define FC1_K   163216       // 16*101*101
#define N_ROI   1024
#define FC1_KBLK 512
#define FC1_NBLK ((FC1_K + FC1_KBLK - 1) / FC1_KBLK)   // 319

typedef unsigned long long u64;

// ---------------- scratch (device globals; no runtime alloc) ----------------
__device__ float g_pool1[B_IMG * 6  * P1 * P1];   // 65.2 MB
__device__ float g_pool2[B_IMG * 16 * P2 * P2];   // 41.8 MB
__device__ float g_fc1_part[320 * 4096];          // split-K partials
__device__ float g_fc1[64 * 64];                  // pre-relu fc1 output
__device__ float g_roi[N_ROI * 3 * 16 * 16];      // roi-pooled maps (3 MB)

// ---------------- packed f32x2 helpers (sm_100+ PTX) ----------------
__device__ __forceinline__ u64 pack2(float lo, float hi) {
    u64 r;
    asm("mov.b64 %0, {%1, %2};" : "=l"(r) : "f"(lo), "f"(hi));
    return r;
}
__device__ __forceinline__ float2 unpack2(u64 v) {
    float2 r;
    asm("mov.b64 {%0, %1}, %2;" : "=f"(r.x), "=f"(r.y) : "l"(v));
    return r;
}
__device__ __forceinline__ u64 ffma2(u64 a, u64 b, u64 c) {
    u64 d;
    asm("fma.rn.f32x2 %0, %1, %2, %3;" : "=l"(d) : "l"(a), "l"(b), "l"(c));
    return d;
}

// ============================================================
// Kernel 1: conv1 (3->6, 5x5, valid) + relu + maxpool2, fused.
// grid (13,13,64), block (16,16). Thread = 1 pooled pixel, all 6 oc.
// oc paired (3 pairs) in f32x2 accumulators; weights pre-paired in smem.
// ============================================================
__global__ __launch_bounds__(256) void conv1_pool_kernel(const float* __restrict__ img,
                                                         const float* __restrict__ w,
                                                         const float* __restrict__ bias)
{
    __shared__ float s_in[3][36][37];    // 15984 B
    __shared__ u64   s_wp[225];          // (ic*25+k)*3 + p  -> (w[2p], w[2p+1])
    const int bx = blockIdx.x, by = blockIdx.y, b = blockIdx.z;
    const int tx = threadIdx.x, ty = threadIdx.y;
    const int tid = ty * 16 + tx;
    const int iy0 = by * 32, ix0 = bx * 32;

    if (tid < 225) {
        int p = tid % 3, rest = tid / 3;
        int k = rest % 25, ic = rest / 25;
        float w0 = w[((2 * p    ) * 3 + ic) * 25 + k];
        float w1 = w[((2 * p + 1) * 3 + ic) * 25 + k];
        s_wp[tid] = pack2(w0, w1);
    }
    for (int i = tid; i < 3 * 36 * 36; i += 256) {
        int ic = i / 1296;
        int r  = i % 1296;
        int yy = r / 36, xx = r % 36;
        int gy = iy0 + yy, gx = ix0 + xx;
        float v = 0.f;
        if (gy < HW && gx < HW)
            v = img[((b * 3 + ic) * HW + gy) * HW + gx];
        s_in[ic][yy][xx] = v;
    }
    __syncthreads();

    u64 acc[3][4];   // [oc-pair][pooled-pos]
#pragma unroll
    for (int p = 0; p < 3; p++)
#pragma unroll
        for (int q = 0; q < 4; q++) acc[p][q] = 0ull;

    for (int ic = 0; ic < 3; ic++) {
        for (int ky = 0; ky < 5; ky++) {
#pragma unroll
            for (int kx = 0; kx < 5; kx++) {
                u64 d[4];
                {
                    float i00 = s_in[ic][2 * ty + ky    ][2 * tx + kx    ];
                    float i01 = s_in[ic][2 * ty + ky    ][2 * tx + kx + 1];
                    float i10 = s_in[ic][2 * ty + ky + 1][2 * tx + kx    ];
                    float i11 = s_in[ic][2 * ty + ky + 1][2 * tx + kx + 1];
                    d[0] = pack2(i00, i00);
                    d[1] = pack2(i01, i01);
                    d[2] = pack2(i10, i10);
                    d[3] = pack2(i11, i11);
                }
                const int base = (ic * 25 + ky * 5 + kx) * 3;
#pragma unroll
                for (int p = 0; p < 3; p++) {
                    u64 w2 = s_wp[base + p];
                    acc[p][0] = ffma2(w2, d[0], acc[p][0]);
                    acc[p][1] = ffma2(w2, d[1], acc[p][1]);
                    acc[p][2] = ffma2(w2, d[2], acc[p][2]);
                    acc[p][3] = ffma2(w2, d[3], acc[p][3]);
                }
            }
        }
    }

    const int py = by * 16 + ty, px = bx * 16 + tx;
    if (py < P1 && px < P1) {
#pragma unroll
        for (int p = 0; p < 3; p++) {
            float2 a0 = unpack2(acc[p][0]);
            float2 a1 = unpack2(acc[p][1]);
            float2 a2 = unpack2(acc[p][2]);
            float2 a3 = unpack2(acc[p][3]);
            float me = fmaxf(fmaxf(a0.x, a1.x), fmaxf(a2.x, a3.x));
            float mo = fmaxf(fmaxf(a0.y, a1.y), fmaxf(a2.y, a3.y));
            int oce = 2 * p, oco = 2 * p + 1;
            g_pool1[((b * 6 + oce) * P1 + py) * P1 + px] = fmaxf(me + __ldg(bias + oce), 0.f);
            g_pool1[((b * 6 + oco) * P1 + py) * P1 + px] = fmaxf(mo + __ldg(bias + oco), 0.f);
        }
    }
}

// ============================================================
// Kernel 2: conv2 (6->16, 5x5, valid) + relu + maxpool2, fused.
// grid (7,7,64), block (16,16). Thread = 1 pooled pixel, 16 oc as 8 f32x2 pairs.
// ============================================================
__global__ __launch_bounds__(256) void conv2_pool_kernel(const float* __restrict__ w,
                                                         const float* __restrict__ bias)
{
    __shared__ float s_in[6][36][37];    // 31968 B
    __shared__ u64   s_wp[1200];         // (ic*25+k)*8 + p   (9600 B)
    const int bx = blockIdx.x, by = blockIdx.y, b = blockIdx.z;
    const int tx = threadIdx.x, ty = threadIdx.y;
    const int tid = ty * 16 + tx;
    const int iy0 = by * 32, ix0 = bx * 32;

    for (int i = tid; i < 1200; i += 256) {
        int p = i & 7, rest = i >> 3;
        int k = rest % 25, ic = rest / 25;
        float w0 = w[((2 * p    ) * 6 + ic) * 25 + k];
        float w1 = w[((2 * p + 1) * 6 + ic) * 25 + k];
        s_wp[i] = pack2(w0, w1);
    }
    for (int i = tid; i < 6 * 36 * 36; i += 256) {
        int ic = i / 1296;
        int r  = i % 1296;
        int yy = r / 36, xx = r % 36;
        int gy = iy0 + yy, gx = ix0 + xx;
        float v = 0.f;
        if (gy < P1 && gx < P1)
            v = g_pool1[((b * 6 + ic) * P1 + gy) * P1 + gx];
        s_in[ic][yy][xx] = v;
    }
    __syncthreads();

    u64 acc[8][4];
#pragma unroll
    for (int p = 0; p < 8; p++)
#pragma unroll
        for (int q = 0; q < 4; q++) acc[p][q] = 0ull;

    for (int ic = 0; ic < 6; ic++) {
        for (int ky = 0; ky < 5; ky++) {
#pragma unroll
            for (int kx = 0; kx < 5; kx++) {
                u64 d[4];
                {
                    float i00 = s_in[ic][2 * ty + ky    ][2 * tx + kx    ];
                    float i01 = s_in[ic][2 * ty + ky    ][2 * tx + kx + 1];
                    float i10 = s_in[ic][2 * ty + ky + 1][2 * tx + kx    ];
                    float i11 = s_in[ic][2 * ty + ky + 1][2 * tx + kx + 1];
                    d[0] = pack2(i00, i00);
                    d[1] = pack2(i01, i01);
                    d[2] = pack2(i10, i10);
                    d[3] = pack2(i11, i11);
                }
                const int base = (ic * 25 + ky * 5 + kx) * 8;
#pragma unroll
                for (int p = 0; p < 8; p++) {
                    u64 w2 = s_wp[base + p];
                    acc[p][0] = ffma2(w2, d[0], acc[p][0]);
                    acc[p][1] = ffma2(w2, d[1], acc[p][1]);
                    acc[p][2] = ffma2(w2, d[2], acc[p][2]);
                    acc[p][3] = ffma2(w2, d[3], acc[p][3]);
                }
            }
        }
    }

    const int py = by * 16 + ty, px = bx * 16 + tx;
    if (py < P2 && px < P2) {
#pragma unroll
        for (int p = 0; p < 8; p++) {
            float2 a0 = unpack2(acc[p][0]);
            float2 a1 = unpack2(acc[p][1]);
            float2 a2 = unpack2(acc[p][2]);
            float2 a3 = unpack2(acc[p][3]);
            float me = fmaxf(fmaxf(a0.x, a1.x), fmaxf(a2.x, a3.x));
            float mo = fmaxf(fmaxf(a0.y, a1.y), fmaxf(a2.y, a3.y));
            int oce = 2 * p, oco = 2 * p + 1;
            g_pool2[((b * 16 + oce) * P2 + py) * P2 + px] = fmaxf(me + __ldg(bias + oce), 0.f);
            g_pool2[((b * 16 + oco) * P2 + py) * P2 + px] = fmaxf(mo + __ldg(bias + oco), 0.f);
        }
    }
}

// ============================================================
// Kernel 3: fc1 GEMM, split-K, deterministic partials.
// Staging vectorized: kb is 64-aligned, FC1_K % 4 == 0 -> float4 legal.
// ============================================================
__global__ __launch_bounds__(256) void fc1_gemm_kernel(const float* __restrict__ w)
{
    __shared__ float xs[64][65];
    __shared__ float ws[64][65];
    const int tid = threadIdx.x;
    const int i = tid >> 4, j = tid & 15;
    const int k0 = blockIdx.x * FC1_KBLK;

    float acc[4][4];
#pragma unroll
    for (int r = 0; r < 4; r++)
#pragma unroll
        for (int s = 0; s < 4; s++) acc[r][s] = 0.f;

    for (int sc = 0; sc < FC1_KBLK / 64; sc++) {
        const int kb = k0 + sc * 64;
        {
            int row  = tid >> 2;          // 0..63
            int quad = tid & 3;           // 0..3
#pragma unroll
            for (int q = 0; q < 4; q++) {
                int kk = (quad + 4 * q) * 4;
                int k  = kb + kk;
                float4 xv = make_float4(0.f, 0.f, 0.f, 0.f);
                float4 wv = make_float4(0.f, 0.f, 0.f, 0.f);
                if (k + 3 < FC1_K) {
                    xv = *reinterpret_cast<const float4*>(&g_pool2[(size_t)row * FC1_K + k]);
                    wv = *reinterpret_cast<const float4*>(&w[(size_t)row * FC1_K + k]);
                } else {
#pragma unroll
                    for (int t = 0; t < 4; t++) {
                        if (k + t < FC1_K) {
                            (&xv.x)[t] = g_pool2[(size_t)row * FC1_K + k + t];
                            (&wv.x)[t] = w[(size_t)row * FC1_K + k + t];
                        }
                    }
                }
                xs[row][kk] = xv.x; xs[row][kk+1] = xv.y; xs[row][kk+2] = xv.z; xs[row][kk+3] = xv.w;
                ws[row][kk] = wv.x; ws[row][kk+1] = wv.y; ws[row][kk+2] = wv.z; ws[row][kk+3] = wv.w;
            }
        }
        __syncthreads();

#pragma unroll 4
        for (int kk = 0; kk < 64; kk++) {
            float a0 = xs[4 * i + 0][kk];
            float a1 = xs[4 * i + 1][kk];
            float a2 = xs[4 * i + 2][kk];
            float a3 = xs[4 * i + 3][kk];
            float b0 = ws[4 * j + 0][kk];
            float b1 = ws[4 * j + 1][kk];
            float b2 = ws[4 * j + 2][kk];
            float b3 = ws[4 * j + 3][kk];
            acc[0][0] = fmaf(a0, b0, acc[0][0]); acc[0][1] = fmaf(a0, b1, acc[0][1]);
            acc[0][2] = fmaf(a0, b2, acc[0][2]); acc[0][3] = fmaf(a0, b3, acc[0][3]);
            acc[1][0] = fmaf(a1, b0, acc[1][0]); acc[1][1] = fmaf(a1, b1, acc[1][1]);
            acc[1][2] = fmaf(a1, b2, acc[1][2]); acc[1][3] = fmaf(a1, b3, acc[1][3]);
            acc[2][0] = fmaf(a2, b0, acc[2][0]); acc[2][1] = fmaf(a2, b1, acc[2][1]);
            acc[2][2] = fmaf(a2, b2, acc[2][2]); acc[2][3] = fmaf(a2, b3, acc[2][3]);
            acc[3][0] = fmaf(a3, b0, acc[3][0]); acc[3][1] = fmaf(a3, b1, acc[3][1]);
            acc[3][2] = fmaf(a3, b2, acc[3][2]); acc[3][3] = fmaf(a3, b3, acc[3][3]);
        }
        __syncthreads();
    }

    float* part = g_fc1_part + (size_t)blockIdx.x * 4096;
#pragma unroll
    for (int r = 0; r < 4; r++)
#pragma unroll
        for (int s = 0; s < 4; s++)
            part[(4 * i + r) * 64 + (4 * j + s)] = acc[r][s];
}

// Ordered reduce of the split-K partials (+bias). Deterministic.
__global__ void fc1_reduce_kernel(const float* __restrict__ fc1_b)
{
    int idx = blockIdx.x * 128 + threadIdx.x;
    if (idx < 4096) {
        float s = fc1_b[idx & 63];
#pragma unroll 16
        for (int p = 0; p < FC1_NBLK; p++)
            s += g_fc1_part[(size_t)p * 4096 + idx];
        g_fc1[idx] = s;   // pre-relu; relu applied at point of use
    }
}

// ============================================================
// Kernel 4: RoI max-pool. grid (N_ROI, 3), block 256 (8 warps).
// Warp per bin; row loop unrolled x4 for MLP.
// ============================================================
__global__ __launch_bounds__(256) void roi_pool_kernel(const float* __restrict__ img)
{
    const int n  = blockIdx.x;
    const int ch = blockIdx.y;
    const int b  = n >> 4;
    const int j  = n & 15;
    const int warp = threadIdx.x >> 5;
    const int lane = threadIdx.x & 31;

    // boxes[n][c] = relu(fc1[b][c*16+j]); c = round(box*0.5) (rint = half-to-even)
    float c0 = rintf(fmaxf(g_fc1[b * 64 +  0 + j], 0.f) * 0.5f);
    float c1 = rintf(fmaxf(g_fc1[b * 64 + 16 + j], 0.f) * 0.5f);
    float c2 = rintf(fmaxf(g_fc1[b * 64 + 32 + j], 0.f) * 0.5f);
    float c3 = rintf(fmaxf(g_fc1[b * 64 + 48 + j], 0.f) * 0.5f);
    float x1 = fminf(fmaxf(c0, 0.f), 415.f);
    float y1 = fminf(fmaxf(c1, 0.f), 415.f);
    float x2 = fminf(fmaxf(c2, 0.f), 415.f);
    float y2 = fminf(fmaxf(c3, 0.f), 415.f);
    float bw = fmaxf(x2 - x1 + 1.f, 1.f) * (1.f / 16.f);
    float bh = fmaxf(y2 - y1 + 1.f, 1.f) * (1.f / 16.f);

    const float* base = img + ((size_t)(b * 3 + ch) * HW) * HW;

    for (int bin = warp; bin < 256; bin += 8) {
        int ph = bin >> 4;
        int pw = bin & 15;
        float fph = (float)ph, fpw = (float)pw;
        int hs  = (int)fminf(fmaxf(floorf(fph * bh) + y1, 0.f), 416.f);
        int he  = (int)fminf(fmaxf(ceilf((fph + 1.f) * bh) + y1, 0.f), 416.f);
        int ws_ = (int)fminf(fmaxf(floorf(fpw * bw) + x1, 0.f), 416.f);
        int we_ = (int)fminf(fmaxf(ceilf((fpw + 1.f) * bw) + x1, 0.f), 416.f);
        int ww  = we_ - ws_;
        float m0 = -1e30f, m1 = -1e30f, m2 = -1e30f, m3 = -1e30f;
        if (lane < ww) {
            const float* col = base + ws_ + lane;
            int h = hs;
            // 4 independent chains -> MLP=4 on the L2 loads
            for (; h + 3 < he; h += 4) {
                float v0 = __ldg(col + (size_t)(h    ) * HW);
                float v1 = __ldg(col + (size_t)(h + 1) * HW);
                float v2 = __ldg(col + (size_t)(h + 2) * HW);
                float v3 = __ldg(col + (size_t)(h + 3) * HW);
                m0 = fmaxf(m0, v0);
                m1 = fmaxf(m1, v1);
                m2 = fmaxf(m2, v2);
                m3 = fmaxf(m3, v3);
            }
            for (; h < he; h++)
                m0 = fmaxf(m0, __ldg(col + (size_t)h * HW));
        }
        float m = fmaxf(fmaxf(m0, m1), fmaxf(m2, m3));
#pragma unroll
        for (int o = 16; o; o >>= 1)
            m = fmaxf(m, __shfl_xor_sync(0xffffffffu, m, o));
        if (lane == 0)
            g_roi[((n * 3 + ch) * 16 + ph) * 16 + pw] = ((he > hs) && (ww > 0)) ? m : 0.f;
    }
}

// ============================================================
// Kernel 5 (tail): per ROI — 4x4 conv (3->1) + relu + fc2 + relu.
// grid N_ROI, block 256. fc2 weights staged in smem (coalesced once).
// ============================================================
__global__ __launch_bounds__(256) void tail2_kernel(const float* __restrict__ roi_w,
                                                    const float* __restrict__ roi_b,
                                                    const float* __restrict__ fc2_w,
                                                    const float* __restrict__ fc2_b,
                                                    float* __restrict__ out)
{
    __shared__ float s_roi[768];       // [ch][16][16]
    __shared__ float s_y[169];
    __shared__ float s_rw[48];
    __shared__ float s_fw[64 * 169];   // 43.3 KB

    const int n = blockIdx.x;
    const int tid = threadIdx.x;

    if (tid < 48) s_rw[tid] = roi_w[tid];
    for (int i = tid; i < 768; i += 256)
        s_roi[i] = g_roi[n * 768 + i];
    for (int i = tid; i < 64 * 169; i += 256)
        s_fw[i] = fc2_w[i];
    __syncthreads();

    // 4x4 conv (3->1, valid): 13x13 outputs + relu
    if (tid < 169) {
        int oy = tid / 13, ox = tid % 13;
        float a = __ldg(roi_b);
#pragma unroll
        for (int ch = 0; ch < 3; ch++)
#pragma unroll
            for (int ky = 0; ky < 4; ky++)
#pragma unroll
                for (int kx = 0; kx < 4; kx++)
                    a = fmaf(s_roi[ch * 256 + (oy + ky) * 16 + (ox + kx)],
                             s_rw[ch * 16 + ky * 4 + kx], a);
        s_y[tid] = fmaxf(a, 0.f);
    }
    __syncthreads();

    // fc2: [169] -> [64], + bias, relu (weights from smem, conflict-free: gcd(169,32)=1)
    if (tid < 64) {
        float a = __ldg(fc2_b + tid);
        const float* wrow = s_fw + tid * 169;
#pragma unroll 13
        for (int k = 0; k < 169; k++)
            a = fmaf(s_y[k], wrow[k], a);
        out[n * 64 + tid] = fmaxf(a, 0.f);
    }
}

// ============================================================
// launch — pure kernel launches, graph-capturable, allocation-free
// ============================================================
extern "C" void kernel_launch(void* const* d_in, const int* in_sizes, int n_in,
                              void* d_out, int out_size)
{
    const float* img       = (const float*)d_in[0];
    const float* conv1_w   = (const float*)d_in[1];
    const float* conv1_b   = (const float*)d_in[2];
    const float* conv2_w   = (const float*)d_in[3];
    const float* conv2_b   = (const float*)d_in[4];
    const float* fc1_w     = (const float*)d_in[5];
    const float* fc1_b     = (const float*)d_in[6];
    const float* roi_w     = (const float*)d_in[7];
    const float* roi_b     = (const float*)d_in[8];
    const float* fc2_w     = (const float*)d_in[9];
    const float* fc2_b     = (const float*)d_in[10];
    float* out = (float*)d_out;

    dim3 blk(16, 16);
    conv1_pool_kernel<<<dim3(13, 13, B_IMG), blk>>>(img, conv1_w, conv1_b);
    conv2_pool_kernel<<<dim3(7, 7, B_IMG), blk>>>(conv2_w, conv2_b);
    fc1_gemm_kernel<<<FC1_NBLK, 256>>>(fc1_w);
    fc1_reduce_kernel<<<32, 128>>>(fc1_b);
    roi_pool_kernel<<<dim3(N_ROI, 3), 256>>>(img);
    tail2_kernel<<<N_ROI, 256>>>(roi_w, roi_b, fc2_w, fc2_b, out);
}